// round 16
// baseline (speedup 1.0000x reference)
#include <cuda_runtime.h>
#include <cuda_bf16.h>
#include <cuda_fp16.h>
#include <cstdint>

// ---------------- problem constants ----------------
#define NN    100000
#define EE    1600000
#define HIDD  128
#define HEADS 8
#define CC    16
#define LAYERS 3

// ---------------- device scratch (no allocs allowed) ----------------
__device__ float  g_h [(size_t)NN * HIDD];
__device__ __half g_h2[(size_t)NN * HIDD];     // fp16 message table
__device__ float  g_y [(size_t)NN * HIDD];
__device__ float  g_alsrc[NN * HEADS];
__device__ float  g_aldst[NN * HEADS];
__device__ int    g_rowptr[NN + 1];
__device__ int    g_fill[NN];                  // zero at entry (tail kernel re-zeros)
__device__ int    g_col[EE];
__device__ int    g_bsums[256];
__device__ float  g_bnsum[LAYERS * HIDD];      // per-layer slices
__device__ float  g_bnsq [LAYERS * HIDD];
// pre-split/transposed/swizzled weight images (bf16 hi/lo), 64-k chunks of 8192 elems
__device__ __nv_bfloat16 g_Bhi[(4 + 2 * LAYERS) * 8192];
__device__ __nv_bfloat16 g_Blo[(4 + 2 * LAYERS) * 8192];

// ---------------- small helpers ----------------
__device__ __forceinline__ float lrelu02(float x) { return x > 0.f ? x : 0.2f * x; }
__device__ __forceinline__ float eluf(float x)    { return x > 0.f ? x : expm1f(x); }

__device__ __forceinline__ void mma_bf16(float* d, const uint32_t* a, const uint32_t* b) {
    asm volatile(
        "mma.sync.aligned.m16n8k16.row.col.f32.bf16.bf16.f32 "
        "{%0,%1,%2,%3}, {%4,%5,%6,%7}, {%8,%9}, {%0,%1,%2,%3};"
        : "+f"(d[0]), "+f"(d[1]), "+f"(d[2]), "+f"(d[3])
        : "r"(a[0]), "r"(a[1]), "r"(a[2]), "r"(a[3]), "r"(b[0]), "r"(b[1]));
}

__device__ __forceinline__ uint32_t cvt_bf16x2(float a, float b) {
    uint32_t r;
    asm("cvt.rn.bf16x2.f32 %0, %1, %2;" : "=r"(r) : "f"(b), "f"(a));
    return r;
}

__device__ __forceinline__ uint32_t smem_addr_u32(const void* p) {
    return (uint32_t)__cvta_generic_to_shared(p);
}
#define CP_ASYNC16(saddr, gptr) \
    asm volatile("cp.async.ca.shared.global [%0], [%1], 16;" :: "r"(saddr), "l"(gptr))
#define CP_ASYNC_COMMIT() asm volatile("cp.async.commit_group;")
#define CP_ASYNC_WAIT0()  asm volatile("cp.async.wait_group 0;")

// ------- prep: weight hi/lo split + zero BN slices (NO histogram — fast path) -------
__global__ void prep_w_kernel(const float* __restrict__ proj_w,
                              const float* __restrict__ Wl,
                              __nv_bfloat16* __restrict__ bhi,
                              __nv_bfloat16* __restrict__ blo,
                              float* __restrict__ bnS, float* __restrict__ bnQ) {
    int t = blockIdx.x * blockDim.x + threadIdx.x;
    if (t < LAYERS * HIDD) { bnS[t] = 0.f; bnQ[t] = 0.f; }
    const int TOTAL = (4 + 2 * LAYERS) * 8192;   // 81920
    if (t >= TOTAL) return;
    int k, n, base;
    const float* src;
    if (t < 32768) {                              // proj: K=256
        k = t >> 7; n = t & 127;
        src = proj_w;
        base = (k >> 6) * 8192;
    } else {
        int u = t - 32768;
        int l = u >> 14;
        int v = u & 16383;
        k = v >> 7; n = v & 127;
        src = Wl + l * (HIDD * HIDD);
        base = 32768 + l * 16384 + (k >> 6) * 8192;
    }
    float w = src[k * HIDD + n];
    __nv_bfloat16 hi = __float2bfloat16_rn(w);
    __nv_bfloat16 lo = __float2bfloat16_rn(w - __bfloat162float(hi));
    int kl = k & 63;
    int byte = n * 128 + ((kl * 2) ^ ((n & 7) << 4));
    bhi[base + (byte >> 1)] = hi;
    blo[base + (byte >> 1)] = lo;
}

// ---------------- CSR build (side stream) ----------------
// g_fill is zero on entry: zero-initialized at module load, re-zeroed by the tail
// kernel of every launch (deterministic: identical work and output every call).
__global__ void hist_kernel(const int* __restrict__ dst, int* __restrict__ cnt, int E) {
    int t = blockIdx.x * blockDim.x + threadIdx.x;
    if (t < E) atomicAdd(&cnt[dst[t]], 1);
}
__global__ void scan_block_kernel(const int* __restrict__ in, int* __restrict__ out,
                                  int* __restrict__ bsums, int n) {
    __shared__ int s[1024];
    int tid = threadIdx.x;
    int gid = blockIdx.x * 1024 + tid;
    s[tid] = (gid < n) ? in[gid] : 0;
    __syncthreads();
    #pragma unroll
    for (int off = 1; off < 1024; off <<= 1) {
        int v = (tid >= off) ? s[tid - off] : 0;
        __syncthreads();
        s[tid] += v;
        __syncthreads();
    }
    if (gid < n) out[gid] = (tid == 0) ? 0 : s[tid - 1];
    if (tid == 1023) bsums[blockIdx.x] = s[1023];
}
__global__ void scan_add_kernel(int* __restrict__ rowptr, int* __restrict__ fill,
                                const int* __restrict__ bsums, int n, int total) {
    __shared__ int s_off;
    int tid = threadIdx.x;
    if (tid < 32) {
        int acc = 0;
        for (int j = tid; j < (int)blockIdx.x; j += 32) acc += bsums[j];
        #pragma unroll
        for (int o = 16; o; o >>= 1) acc += __shfl_xor_sync(0xffffffffu, acc, o);
        if (tid == 0) s_off = acc;
    }
    __syncthreads();
    int gid = blockIdx.x * 1024 + tid;
    if (gid < n) {
        int v = rowptr[gid] + s_off;
        rowptr[gid] = v;
        fill[gid]   = v;
    }
    if (gid == 0) rowptr[n] = total;
}
__global__ void scatter_kernel(const int* __restrict__ src, const int* __restrict__ dst,
                               int* __restrict__ fill, int* __restrict__ col, int E) {
    int t = blockIdx.x * blockDim.x + threadIdx.x;
    if (t < E) {
        int d = dst[t];
        int p = atomicAdd(&fill[d], 1);
        col[p] = src[t];
    }
}

// ------------- mma.sync bf16x3 GEMM: C[M,128] = A[M,KCH*64] @ W -------------
// MODE 0: Cf = elu(A@W + bias)                       (proj)
// MODE 1: Ch = A@W (fp16) + fused al dots            (layer 0)
// MODE 2: MODE 1, but A-fill computes h = elu(y*sc+sh) + h in-flight (fused BN apply)
template<int KCH, int MODE>
__global__ __launch_bounds__(256, 2)
void tc_gemm_kernel(float* __restrict__ A, const float* __restrict__ Yv,
                    const float* __restrict__ bnsum, const float* __restrict__ bnsq,
                    const float* __restrict__ bng, const float* __restrict__ bnb,
                    const __nv_bfloat16* __restrict__ Bhi_g,
                    const __nv_bfloat16* __restrict__ Blo_g,
                    const float* __restrict__ aux0, const float* __restrict__ aux1,
                    float* __restrict__ Cf, __half* __restrict__ Ch,
                    float* __restrict__ alsrc, float* __restrict__ aldst, int M) {
    extern __shared__ __align__(256) char dyn[];
    char* Ah = dyn;                  // 16 KB: A hi, 128 rows x 128 B
    char* Al = dyn + 16384;          // 16 KB: A lo
    char* Bh = dyn + 32768;          // 16 KB: B hi, [n][k]
    char* Bl = dyn + 49152;          // 16 KB: B lo
    __shared__ float s_as[HIDD], s_ad[HIDD], s_sc[HIDD], s_sh[HIDD];

    int tid = threadIdx.x, wid = tid >> 5, lane = tid & 31;
    int g = lane >> 2, t = lane & 3;
    int bm = blockIdx.x * 128;
    int mrow0 = (wid & 3) * 32;
    int ncol0 = (wid >> 2) * 64;

    if (tid < HIDD) {
        s_as[tid] = aux0 ? aux0[tid] : 0.f;
        s_ad[tid] = aux1 ? aux1[tid] : 0.f;
        if (MODE == 2) {
            float mu  = bnsum[tid] * (1.f / NN);
            float var = bnsq[tid] * (1.f / NN) - mu * mu;
            float sc  = bng[tid] * rsqrtf(var + 1e-5f);
            s_sc[tid] = sc;
            s_sh[tid] = bnb[tid] - mu * sc;
        }
    }
    if (MODE == 2) __syncthreads();

    float d[2][8][4];
    #pragma unroll
    for (int mt = 0; mt < 2; mt++)
        #pragma unroll
        for (int nt = 0; nt < 8; nt++)
            #pragma unroll
            for (int e = 0; e < 4; e++) d[mt][nt][e] = 0.f;

    #pragma unroll 1
    for (int c = 0; c < KCH; c++) {
        if (c > 0) __syncthreads();
        // ---- B chunk via cp.async (overlaps with A fill below) ----
        {
            const char* bh_src = (const char*)(Bhi_g + c * 8192);
            const char* bl_src = (const char*)(Blo_g + c * 8192);
            #pragma unroll
            for (int i = 0; i < 4; i++) {
                int byte = (tid + i * 256) * 16;
                CP_ASYNC16(smem_addr_u32(Bh + byte), bh_src + byte);
                CP_ASYNC16(smem_addr_u32(Bl + byte), bl_src + byte);
            }
            CP_ASYNC_COMMIT();
        }
        // ---- fill A chunk: 128 rows x 64 k floats -> bf16 hi/lo (truncation split) ----
        #pragma unroll
        for (int i = 0; i < 4; i++) {
            int li = tid + i * 256;            // 0..1023
            int r  = li >> 3;                  // row 0..127
            int gq = li & 7;                   // 16B group (8 bf16)
            int grow = bm + r;
            float v[8] = {0.f, 0.f, 0.f, 0.f, 0.f, 0.f, 0.f, 0.f};
            if (grow < M) {
                if (MODE == 2) {
                    int cb = c * 64 + gq * 8;
                    const float* yp = Yv + (size_t)grow * HIDD + cb;
                    float* hp = A + (size_t)grow * HIDD + cb;
                    float4 y0 = *(const float4*)(yp);
                    float4 y1 = *(const float4*)(yp + 4);
                    float4 h0 = *(const float4*)(hp);
                    float4 h1 = *(const float4*)(hp + 4);
                    v[0] = eluf(fmaf(y0.x, s_sc[cb + 0], s_sh[cb + 0])) + h0.x;
                    v[1] = eluf(fmaf(y0.y, s_sc[cb + 1], s_sh[cb + 1])) + h0.y;
                    v[2] = eluf(fmaf(y0.z, s_sc[cb + 2], s_sh[cb + 2])) + h0.z;
                    v[3] = eluf(fmaf(y0.w, s_sc[cb + 3], s_sh[cb + 3])) + h0.w;
                    v[4] = eluf(fmaf(y1.x, s_sc[cb + 4], s_sh[cb + 4])) + h1.x;
                    v[5] = eluf(fmaf(y1.y, s_sc[cb + 5], s_sh[cb + 5])) + h1.y;
                    v[6] = eluf(fmaf(y1.z, s_sc[cb + 6], s_sh[cb + 6])) + h1.z;
                    v[7] = eluf(fmaf(y1.w, s_sc[cb + 7], s_sh[cb + 7])) + h1.w;
                    *(float4*)(hp)     = make_float4(v[0], v[1], v[2], v[3]);
                    *(float4*)(hp + 4) = make_float4(v[4], v[5], v[6], v[7]);
                } else {
                    const float* ap = A + (size_t)grow * (KCH * 64) + c * 64 + gq * 8;
                    float4 f0 = *(const float4*)(ap);
                    float4 f1 = *(const float4*)(ap + 4);
                    v[0] = f0.x; v[1] = f0.y; v[2] = f0.z; v[3] = f0.w;
                    v[4] = f1.x; v[5] = f1.y; v[6] = f1.z; v[7] = f1.w;
                }
            }
            uint4 H, L;
            uint32_t* hp4 = &H.x;
            uint32_t* lp4 = &L.x;
            #pragma unroll
            for (int e = 0; e < 4; e++) {
                uint32_t b0 = __float_as_uint(v[2 * e]);
                uint32_t b1 = __float_as_uint(v[2 * e + 1]);
                hp4[e] = __byte_perm(b0, b1, 0x7632);     // {b0.hi16, b1.hi16}
                float lo0 = v[2 * e]     - __uint_as_float(b0 & 0xFFFF0000u);
                float lo1 = v[2 * e + 1] - __uint_as_float(b1 & 0xFFFF0000u);
                lp4[e] = cvt_bf16x2(lo0, lo1);
            }
            int byte = r * 128 + ((gq * 16) ^ ((r & 7) << 4));
            *(uint4*)(Ah + byte) = H;
            *(uint4*)(Al + byte) = L;
        }
        CP_ASYNC_WAIT0();
        __syncthreads();

        // ---- compute: 4 ksteps x 3 split terms x 16 mma ----
        #pragma unroll 1
        for (int ks = 0; ks < 4; ks++) {
            int k0 = ks * 32 + 4 * t;
            int k2 = k0 + 16;
            uint32_t ahi[2][4], alo[2][4];
            #pragma unroll
            for (int mt = 0; mt < 2; mt++) {
                int r0 = mrow0 + mt * 16 + g;
                int sw = (r0 & 7) << 4;
                int b0 = r0 * 128, b1 = b0 + 1024;
                ahi[mt][0] = *(const uint32_t*)(Ah + b0 + (k0 ^ sw));
                ahi[mt][1] = *(const uint32_t*)(Ah + b1 + (k0 ^ sw));
                ahi[mt][2] = *(const uint32_t*)(Ah + b0 + (k2 ^ sw));
                ahi[mt][3] = *(const uint32_t*)(Ah + b1 + (k2 ^ sw));
                alo[mt][0] = *(const uint32_t*)(Al + b0 + (k0 ^ sw));
                alo[mt][1] = *(const uint32_t*)(Al + b1 + (k0 ^ sw));
                alo[mt][2] = *(const uint32_t*)(Al + b0 + (k2 ^ sw));
                alo[mt][3] = *(const uint32_t*)(Al + b1 + (k2 ^ sw));
            }
            #pragma unroll
            for (int t3 = 0; t3 < 3; t3++) {     // hi*Bhi, lo*Bhi, hi*Blo
                const char* Bs = (t3 == 2) ? Bl : Bh;
                #pragma unroll
                for (int nt = 0; nt < 8; nt++) {
                    int n = ncol0 + nt * 8 + g;
                    int sw = (n & 7) << 4;
                    int bb = n * 128;
                    uint32_t b2[2];
                    b2[0] = *(const uint32_t*)(Bs + bb + (k0 ^ sw));
                    b2[1] = *(const uint32_t*)(Bs + bb + (k2 ^ sw));
                    mma_bf16(d[0][nt], (t3 == 1) ? alo[0] : ahi[0], b2);
                    mma_bf16(d[1][nt], (t3 == 1) ? alo[1] : ahi[1], b2);
                }
            }
        }
    }

    // ---- epilogue ----
    #pragma unroll
    for (int mt = 0; mt < 2; mt++) {
        #pragma unroll
        for (int half = 0; half < 2; half++) {
            int row = bm + mrow0 + mt * 16 + g + half * 8;
            if (MODE == 0) {
                if (row < M) {
                    #pragma unroll
                    for (int nt = 0; nt < 8; nt++) {
                        int col = ncol0 + nt * 8 + 2 * t;
                        float2 o;
                        o.x = eluf(d[mt][nt][half * 2]     + s_as[col]);
                        o.y = eluf(d[mt][nt][half * 2 + 1] + s_as[col + 1]);
                        *(float2*)(Cf + (size_t)row * HIDD + col) = o;
                    }
                }
            } else {
                float ss[4] = {0.f, 0.f, 0.f, 0.f};
                float sd[4] = {0.f, 0.f, 0.f, 0.f};
                #pragma unroll
                for (int nt = 0; nt < 8; nt++) {
                    int col = ncol0 + nt * 8 + 2 * t;
                    float dA = d[mt][nt][half * 2];
                    float dB = d[mt][nt][half * 2 + 1];
                    if (row < M)
                        *(__half2*)(Ch + (size_t)row * HIDD + col) = __floats2half2_rn(dA, dB);
                    int hh = nt >> 1;
                    ss[hh] = fmaf(dA, s_as[col], fmaf(dB, s_as[col + 1], ss[hh]));
                    sd[hh] = fmaf(dA, s_ad[col], fmaf(dB, s_ad[col + 1], sd[hh]));
                }
                #pragma unroll
                for (int e = 0; e < 4; e++) {
                    ss[e] += __shfl_xor_sync(0xffffffffu, ss[e], 1);
                    ss[e] += __shfl_xor_sync(0xffffffffu, ss[e], 2);
                    sd[e] += __shfl_xor_sync(0xffffffffu, sd[e], 1);
                    sd[e] += __shfl_xor_sync(0xffffffffu, sd[e], 2);
                }
                if (t == 0 && row < M) {
                    int h0 = ncol0 >> 4;
                    *(float4*)(alsrc + row * 8 + h0) = make_float4(ss[0], ss[1], ss[2], ss[3]);
                    *(float4*)(aldst + row * 8 + h0) = make_float4(sd[0], sd[1], sd[2], sd[3]);
                }
            }
        }
    }
}

// ---------- persistent single-pass softmax aggregate + fused BN channel sums ----------
__global__ __launch_bounds__(256)
void gat_agg_kernel(const __half* __restrict__ h2, const float* __restrict__ alsrc,
                    const float* __restrict__ aldst, const int* __restrict__ rowptr,
                    const int* __restrict__ colidx, const float* __restrict__ convb,
                    float* __restrict__ y, float* __restrict__ bnsum,
                    float* __restrict__ bnsq) {
    int tid = threadIdx.x, wid = tid >> 5, lane = tid & 31;
    int hd = lane >> 2;
    const float4 cb = *(const float4*)(convb + lane * 4);

    float4 S = make_float4(0.f, 0.f, 0.f, 0.f);
    float4 Q = make_float4(0.f, 0.f, 0.f, 0.f);

    int stride = gridDim.x * 8;
    for (int node = blockIdx.x * 8 + wid; node < NN; node += stride) {
        float adn = aldst[node * HEADS + hd];
        float wself = __expf(lrelu02(alsrc[node * HEADS + hd] + adn));
        float denom = wself;

        uint2 hvr = *(const uint2*)(h2 + (size_t)node * HIDD + lane * 4);
        float2 v0 = __half22float2(*reinterpret_cast<__half2*>(&hvr.x));
        float2 v1 = __half22float2(*reinterpret_cast<__half2*>(&hvr.y));
        float4 acc = make_float4(wself * v0.x, wself * v0.y, wself * v1.x, wself * v1.y);

        int s0 = rowptr[node], s1 = rowptr[node + 1];
        #pragma unroll 4
        for (int i = s0; i < s1; i++) {
            int s = colidx[i];
            float wgt = __expf(lrelu02(alsrc[s * HEADS + hd] + adn));
            denom += wgt;
            uint2 ur = *(const uint2*)(h2 + (size_t)s * HIDD + lane * 4);
            float2 u0 = __half22float2(*reinterpret_cast<__half2*>(&ur.x));
            float2 u1 = __half22float2(*reinterpret_cast<__half2*>(&ur.y));
            acc.x = fmaf(wgt, u0.x, acc.x);
            acc.y = fmaf(wgt, u0.y, acc.y);
            acc.z = fmaf(wgt, u1.x, acc.z);
            acc.w = fmaf(wgt, u1.y, acc.w);
        }
        float inv = 1.f / (denom + 1e-16f);
        float4 o = make_float4(acc.x * inv + cb.x, acc.y * inv + cb.y,
                               acc.z * inv + cb.z, acc.w * inv + cb.w);
        *(float4*)(y + (size_t)node * HIDD + lane * 4) = o;
        S.x += o.x; S.y += o.y; S.z += o.z; S.w += o.w;
        Q.x = fmaf(o.x, o.x, Q.x); Q.y = fmaf(o.y, o.y, Q.y);
        Q.z = fmaf(o.z, o.z, Q.z); Q.w = fmaf(o.w, o.w, Q.w);
    }

    __shared__ float4 red[2][8][32];
    red[0][wid][lane] = S;
    red[1][wid][lane] = Q;
    __syncthreads();
    if (wid < 2) {
        float4 a = red[wid][0][lane];
        #pragma unroll
        for (int w = 1; w < 8; w++) {
            float4 b = red[wid][w][lane];
            a.x += b.x; a.y += b.y; a.z += b.z; a.w += b.w;
        }
        float* dst = wid ? bnsq : bnsum;
        atomicAdd(&dst[lane * 4 + 0], a.x);
        atomicAdd(&dst[lane * 4 + 1], a.y);
        atomicAdd(&dst[lane * 4 + 2], a.z);
        atomicAdd(&dst[lane * 4 + 3], a.w);
    }
}

// ---- tail: bn apply (inline bn_final) + fused fc + re-zero fill for next launch ----
__global__ __launch_bounds__(256)
void bn_apply_fc_kernel(const float* __restrict__ y, const float* __restrict__ bnsum,
                        const float* __restrict__ bnsq, const float* __restrict__ bg,
                        const float* __restrict__ bb, float* __restrict__ h,
                        const float* __restrict__ fcw, const float* __restrict__ fcb,
                        float* __restrict__ out, int* __restrict__ fill) {
    __shared__ float s_sc[HIDD], s_sh[HIDD];
    int tid = threadIdx.x;
    int g2 = blockIdx.x * 256 + tid;
    if (g2 < NN) fill[g2] = 0;          // histogram zero for next launch
    if (tid < HIDD) {
        float mu  = bnsum[tid] * (1.f / NN);
        float var = bnsq[tid] * (1.f / NN) - mu * mu;
        float sc  = bg[tid] * rsqrtf(var + 1e-5f);
        s_sc[tid] = sc;
        s_sh[tid] = bb[tid] - mu * sc;
    }
    __syncthreads();
    int node = blockIdx.x * 8 + (tid >> 5);
    if (node >= NN) return;
    int lane = tid & 31;
    int c0 = lane * 4;
    size_t off = (size_t)node * HIDD + c0;
    float4 yv = *(const float4*)(y + off);
    float4 hv = *(const float4*)(h + off);
    float4 o;
    o.x = eluf(fmaf(yv.x, s_sc[c0 + 0], s_sh[c0 + 0])) + hv.x;
    o.y = eluf(fmaf(yv.y, s_sc[c0 + 1], s_sh[c0 + 1])) + hv.y;
    o.z = eluf(fmaf(yv.z, s_sc[c0 + 2], s_sh[c0 + 2])) + hv.z;
    o.w = eluf(fmaf(yv.w, s_sc[c0 + 3], s_sh[c0 + 3])) + hv.w;
    float4 wv = *(const float4*)(fcw + c0);
    float s = o.x * wv.x + o.y * wv.y + o.z * wv.z + o.w * wv.w;
    #pragma unroll
    for (int k = 16; k; k >>= 1) s += __shfl_xor_sync(0xffffffffu, s, k);
    if (lane == 0) out[node] = s + fcb[0];
}

// ---------------- launch ----------------
extern "C" void kernel_launch(void* const* d_in, const int* in_sizes, int n_in,
                              void* d_out, int out_size) {
    const float* x       = (const float*)d_in[0];
    const int*   ei      = (const int*)  d_in[1];
    const float* proj_w  = (const float*)d_in[2];
    const float* proj_b  = (const float*)d_in[3];
    const float* Wl      = (const float*)d_in[4];
    const float* att_src = (const float*)d_in[5];
    const float* att_dst = (const float*)d_in[6];
    const float* conv_b  = (const float*)d_in[7];
    const float* bn_g    = (const float*)d_in[8];
    const float* bn_b    = (const float*)d_in[9];
    const float* fc_w    = (const float*)d_in[10];
    const float* fc_b    = (const float*)d_in[11];
    float* out = (float*)d_out;

    int E = in_sizes[1] / 2;
    const int* srcA = ei;
    const int* dstA = ei + E;

    float *p_h, *p_y, *p_alsrc, *p_aldst, *p_bnsum, *p_bnsq;
    __half* p_h2;
    __nv_bfloat16 *p_bhi, *p_blo;
    int *p_rowptr, *p_fill, *p_col, *p_bsums;
    cudaGetSymbolAddress((void**)&p_h,      g_h);
    cudaGetSymbolAddress((void**)&p_h2,     g_h2);
    cudaGetSymbolAddress((void**)&p_y,      g_y);
    cudaGetSymbolAddress((void**)&p_alsrc,  g_alsrc);
    cudaGetSymbolAddress((void**)&p_aldst,  g_aldst);
    cudaGetSymbolAddress((void**)&p_rowptr, g_rowptr);
    cudaGetSymbolAddress((void**)&p_fill,   g_fill);
    cudaGetSymbolAddress((void**)&p_col,    g_col);
    cudaGetSymbolAddress((void**)&p_bsums,  g_bsums);
    cudaGetSymbolAddress((void**)&p_bnsum,  g_bnsum);
    cudaGetSymbolAddress((void**)&p_bnsq,   g_bnsq);
    cudaGetSymbolAddress((void**)&p_bhi,    g_Bhi);
    cudaGetSymbolAddress((void**)&p_blo,    g_Blo);

    const int SMEM_GEMM = 65536;
    cudaFuncSetAttribute(tc_gemm_kernel<4, 0>,
                         cudaFuncAttributeMaxDynamicSharedMemorySize, SMEM_GEMM);
    cudaFuncSetAttribute(tc_gemm_kernel<2, 1>,
                         cudaFuncAttributeMaxDynamicSharedMemorySize, SMEM_GEMM);
    cudaFuncSetAttribute(tc_gemm_kernel<2, 2>,
                         cudaFuncAttributeMaxDynamicSharedMemorySize, SMEM_GEMM);

    int mblk = (NN + 127) / 128;
    int eblk = (E + 255) / 256;
    const int AGG_GRID = 1184;

    // ---- fork: CSR chain on side stream, concurrent with weight-prep + GEMMs ----
    cudaStream_t s2;
    cudaStreamCreateWithFlags(&s2, cudaStreamNonBlocking);
    cudaEvent_t evFork, evJoin;
    cudaEventCreateWithFlags(&evFork, cudaEventDisableTiming);
    cudaEventCreateWithFlags(&evJoin, cudaEventDisableTiming);
    cudaEventRecord(evFork, 0);
    cudaStreamWaitEvent(s2, evFork, 0);

    // side stream: CSR build (fill is zero at entry; tail re-zeros each launch)
    hist_kernel<<<eblk, 256, 0, s2>>>(dstA, p_fill, E);
    int nblk = (NN + 1023) / 1024;
    scan_block_kernel<<<nblk, 1024, 0, s2>>>(p_fill, p_rowptr, p_bsums, NN);
    scan_add_kernel<<<nblk, 1024, 0, s2>>>(p_rowptr, p_fill, p_bsums, NN, E);
    scatter_kernel<<<eblk, 256, 0, s2>>>(srcA, dstA, p_fill, p_col, E);
    cudaEventRecord(evJoin, s2);

    // main stream: weight prep (fast) + proj + layer-0 GEMM
    prep_w_kernel<<<320, 256>>>(proj_w, Wl, p_bhi, p_blo, p_bnsum, p_bnsq);
    tc_gemm_kernel<4, 0><<<mblk, 256, SMEM_GEMM>>>(
        (float*)x, nullptr, nullptr, nullptr, nullptr, nullptr,
        p_bhi, p_blo, proj_b, nullptr, p_h, nullptr, nullptr, nullptr, NN);
    tc_gemm_kernel<2, 1><<<mblk, 256, SMEM_GEMM>>>(
        p_h, nullptr, nullptr, nullptr, nullptr, nullptr,
        p_bhi + 32768, p_blo + 32768,
        att_src, att_dst, nullptr, p_h2, p_alsrc, p_aldst, NN);

    cudaStreamWaitEvent(0, evJoin, 0);   // CSR ready before first aggregate

    for (int l = 0; l < LAYERS; l++) {
        if (l > 0) {
            // fused: h = elu(y*sc+sh)+h (BN of layer l-1) inside the A-fill
            tc_gemm_kernel<2, 2><<<mblk, 256, SMEM_GEMM>>>(
                p_h, p_y, p_bnsum + (l - 1) * HIDD, p_bnsq + (l - 1) * HIDD,
                bn_g + (l - 1) * HIDD, bn_b + (l - 1) * HIDD,
                p_bhi + 32768 + l * 16384, p_blo + 32768 + l * 16384,
                att_src + l * HEADS * CC, att_dst + l * HEADS * CC,
                nullptr, p_h2, p_alsrc, p_aldst, NN);
        }
        gat_agg_kernel<<<AGG_GRID, 256>>>(p_h2, p_alsrc, p_aldst, p_rowptr, p_col,
                                          conv_b + l * HIDD, p_y,
                                          p_bnsum + l * HIDD, p_bnsq + l * HIDD);
    }

    // ---- tail: BN(layer 2) + residual + fc + fill re-zero ----
    bn_apply_fc_kernel<<<(NN + 7) / 8, 256>>>(
        p_y, p_bnsum + 2 * HIDD, p_bnsq + 2 * HIDD, bn_g + 2 * HIDD, bn_b + 2 * HIDD,
        p_h, fc_w, fc_b, out, p_fill);

    cudaEventDestroy(evFork);
    cudaEventDestroy(evJoin);
    cudaStreamDestroy(s2);
}

// round 17
// speedup vs baseline: 1.0042x; 1.0042x over previous
#include <cuda_runtime.h>
#include <cuda_bf16.h>
#include <cuda_fp16.h>
#include <cstdint>

// ---------------- problem constants ----------------
#define NN    100000
#define EE    1600000
#define HIDD  128
#define HEADS 8
#define CC    16
#define LAYERS 3

// ---------------- device scratch (no allocs allowed) ----------------
__device__ float  g_h [(size_t)NN * HIDD];
__device__ __half g_h2[(size_t)NN * HIDD];     // fp16 message table
__device__ float  g_y [(size_t)NN * HIDD];
__device__ float  g_alsrc[NN * HEADS];
__device__ float  g_aldst[NN * HEADS];
__device__ int    g_rowptr[NN + 1];
__device__ int    g_fill[NN];                  // zero at entry (tail kernel re-zeros)
__device__ int    g_col[EE];
__device__ int    g_bsums[256];
__device__ float  g_bnsum[LAYERS * HIDD];      // per-layer slices
__device__ float  g_bnsq [LAYERS * HIDD];
// pre-split/transposed/swizzled weight images (bf16 hi/lo), 64-k chunks of 8192 elems
__device__ __nv_bfloat16 g_Bhi[(4 + 2 * LAYERS) * 8192];
__device__ __nv_bfloat16 g_Blo[(4 + 2 * LAYERS) * 8192];

// ---------------- small helpers ----------------
__device__ __forceinline__ float lrelu02(float x) { return x > 0.f ? x : 0.2f * x; }
__device__ __forceinline__ float eluf(float x)    { return x > 0.f ? x : expm1f(x); }

__device__ __forceinline__ void mma_bf16(float* d, const uint32_t* a, const uint32_t* b) {
    asm volatile(
        "mma.sync.aligned.m16n8k16.row.col.f32.bf16.bf16.f32 "
        "{%0,%1,%2,%3}, {%4,%5,%6,%7}, {%8,%9}, {%0,%1,%2,%3};"
        : "+f"(d[0]), "+f"(d[1]), "+f"(d[2]), "+f"(d[3])
        : "r"(a[0]), "r"(a[1]), "r"(a[2]), "r"(a[3]), "r"(b[0]), "r"(b[1]));
}

__device__ __forceinline__ uint32_t cvt_bf16x2(float a, float b) {
    uint32_t r;
    asm("cvt.rn.bf16x2.f32 %0, %1, %2;" : "=r"(r) : "f"(b), "f"(a));
    return r;
}

__device__ __forceinline__ uint32_t smem_addr_u32(const void* p) {
    return (uint32_t)__cvta_generic_to_shared(p);
}
#define CP_ASYNC16(saddr, gptr) \
    asm volatile("cp.async.ca.shared.global [%0], [%1], 16;" :: "r"(saddr), "l"(gptr))
#define CP_ASYNC_COMMIT() asm volatile("cp.async.commit_group;")
#define CP_ASYNC_WAIT0()  asm volatile("cp.async.wait_group 0;")

// ------- prep: weight hi/lo split + zero BN slices (NO histogram — fast path) -------
__global__ void prep_w_kernel(const float* __restrict__ proj_w,
                              const float* __restrict__ Wl,
                              __nv_bfloat16* __restrict__ bhi,
                              __nv_bfloat16* __restrict__ blo,
                              float* __restrict__ bnS, float* __restrict__ bnQ) {
    int t = blockIdx.x * blockDim.x + threadIdx.x;
    if (t < LAYERS * HIDD) { bnS[t] = 0.f; bnQ[t] = 0.f; }
    const int TOTAL = (4 + 2 * LAYERS) * 8192;   // 81920
    if (t >= TOTAL) return;
    int k, n, base;
    const float* src;
    if (t < 32768) {                              // proj: K=256
        k = t >> 7; n = t & 127;
        src = proj_w;
        base = (k >> 6) * 8192;
    } else {
        int u = t - 32768;
        int l = u >> 14;
        int v = u & 16383;
        k = v >> 7; n = v & 127;
        src = Wl + l * (HIDD * HIDD);
        base = 32768 + l * 16384 + (k >> 6) * 8192;
    }
    float w = src[k * HIDD + n];
    __nv_bfloat16 hi = __float2bfloat16_rn(w);
    __nv_bfloat16 lo = __float2bfloat16_rn(w - __bfloat162float(hi));
    int kl = k & 63;
    int byte = n * 128 + ((kl * 2) ^ ((n & 7) << 4));
    bhi[base + (byte >> 1)] = hi;
    blo[base + (byte >> 1)] = lo;
}

// ---------------- CSR build (side stream) ----------------
// g_fill is zero on entry: zero-initialized at module load, re-zeroed by the tail
// kernel of every launch (deterministic: identical work and output every call).
__global__ void hist_kernel(const int* __restrict__ dst, int* __restrict__ cnt, int E) {
    int t = blockIdx.x * blockDim.x + threadIdx.x;
    if (t < E) atomicAdd(&cnt[dst[t]], 1);
}
__global__ void scan_block_kernel(const int* __restrict__ in, int* __restrict__ out,
                                  int* __restrict__ bsums, int n) {
    __shared__ int s[1024];
    int tid = threadIdx.x;
    int gid = blockIdx.x * 1024 + tid;
    s[tid] = (gid < n) ? in[gid] : 0;
    __syncthreads();
    #pragma unroll
    for (int off = 1; off < 1024; off <<= 1) {
        int v = (tid >= off) ? s[tid - off] : 0;
        __syncthreads();
        s[tid] += v;
        __syncthreads();
    }
    if (gid < n) out[gid] = (tid == 0) ? 0 : s[tid - 1];
    if (tid == 1023) bsums[blockIdx.x] = s[1023];
}
__global__ void scan_add_kernel(int* __restrict__ rowptr, int* __restrict__ fill,
                                const int* __restrict__ bsums, int n, int total) {
    __shared__ int s_off;
    int tid = threadIdx.x;
    if (tid < 32) {
        int acc = 0;
        for (int j = tid; j < (int)blockIdx.x; j += 32) acc += bsums[j];
        #pragma unroll
        for (int o = 16; o; o >>= 1) acc += __shfl_xor_sync(0xffffffffu, acc, o);
        if (tid == 0) s_off = acc;
    }
    __syncthreads();
    int gid = blockIdx.x * 1024 + tid;
    if (gid < n) {
        int v = rowptr[gid] + s_off;
        rowptr[gid] = v;
        fill[gid]   = v;
    }
    if (gid == 0) rowptr[n] = total;
}
__global__ void scatter_kernel(const int* __restrict__ src, const int* __restrict__ dst,
                               int* __restrict__ fill, int* __restrict__ col, int E) {
    int t = blockIdx.x * blockDim.x + threadIdx.x;
    if (t < E) {
        int d = dst[t];
        int p = atomicAdd(&fill[d], 1);
        col[p] = src[t];
    }
}

// ------------- mma.sync bf16x3 GEMM: C[M,128] = A[M,KCH*64] @ W -------------
// MODE 0: Cf = elu(A@W + bias)                       (proj)
// MODE 1: Ch = A@W (fp16) + fused al dots            (layer 0)
// MODE 2: MODE 1, but A-fill computes h = elu(y*sc+sh) + h in-flight (fused BN apply)
template<int KCH, int MODE>
__global__ __launch_bounds__(256, 2)
void tc_gemm_kernel(float* __restrict__ A, const float* __restrict__ Yv,
                    const float* __restrict__ bnsum, const float* __restrict__ bnsq,
                    const float* __restrict__ bng, const float* __restrict__ bnb,
                    const __nv_bfloat16* __restrict__ Bhi_g,
                    const __nv_bfloat16* __restrict__ Blo_g,
                    const float* __restrict__ aux0, const float* __restrict__ aux1,
                    float* __restrict__ Cf, __half* __restrict__ Ch,
                    float* __restrict__ alsrc, float* __restrict__ aldst, int M) {
    extern __shared__ __align__(256) char dyn[];
    char* Ah = dyn;                  // 16 KB: A hi, 128 rows x 128 B
    char* Al = dyn + 16384;          // 16 KB: A lo
    char* Bh = dyn + 32768;          // 16 KB: B hi, [n][k]
    char* Bl = dyn + 49152;          // 16 KB: B lo
    __shared__ float s_as[HIDD], s_ad[HIDD], s_sc[HIDD], s_sh[HIDD];

    int tid = threadIdx.x, wid = tid >> 5, lane = tid & 31;
    int g = lane >> 2, t = lane & 3;
    int bm = blockIdx.x * 128;
    int mrow0 = (wid & 3) * 32;
    int ncol0 = (wid >> 2) * 64;

    if (tid < HIDD) {
        s_as[tid] = aux0 ? aux0[tid] : 0.f;
        s_ad[tid] = aux1 ? aux1[tid] : 0.f;
        if (MODE == 2) {
            float mu  = bnsum[tid] * (1.f / NN);
            float var = bnsq[tid] * (1.f / NN) - mu * mu;
            float sc  = bng[tid] * rsqrtf(var + 1e-5f);
            s_sc[tid] = sc;
            s_sh[tid] = bnb[tid] - mu * sc;
        }
    }
    if (MODE == 2) __syncthreads();

    float d[2][8][4];
    #pragma unroll
    for (int mt = 0; mt < 2; mt++)
        #pragma unroll
        for (int nt = 0; nt < 8; nt++)
            #pragma unroll
            for (int e = 0; e < 4; e++) d[mt][nt][e] = 0.f;

    #pragma unroll 1
    for (int c = 0; c < KCH; c++) {
        if (c > 0) __syncthreads();
        // ---- B chunk via cp.async (overlaps with A fill below) ----
        {
            const char* bh_src = (const char*)(Bhi_g + c * 8192);
            const char* bl_src = (const char*)(Blo_g + c * 8192);
            #pragma unroll
            for (int i = 0; i < 4; i++) {
                int byte = (tid + i * 256) * 16;
                CP_ASYNC16(smem_addr_u32(Bh + byte), bh_src + byte);
                CP_ASYNC16(smem_addr_u32(Bl + byte), bl_src + byte);
            }
            CP_ASYNC_COMMIT();
        }
        // ---- fill A chunk: 128 rows x 64 k floats -> bf16 hi/lo (truncation split) ----
        #pragma unroll
        for (int i = 0; i < 4; i++) {
            int li = tid + i * 256;            // 0..1023
            int r  = li >> 3;                  // row 0..127
            int gq = li & 7;                   // 16B group (8 bf16)
            int grow = bm + r;
            float v[8] = {0.f, 0.f, 0.f, 0.f, 0.f, 0.f, 0.f, 0.f};
            if (grow < M) {
                if (MODE == 2) {
                    int cb = c * 64 + gq * 8;
                    const float* yp = Yv + (size_t)grow * HIDD + cb;
                    float* hp = A + (size_t)grow * HIDD + cb;
                    float4 y0 = *(const float4*)(yp);
                    float4 y1 = *(const float4*)(yp + 4);
                    float4 h0 = *(const float4*)(hp);
                    float4 h1 = *(const float4*)(hp + 4);
                    v[0] = eluf(fmaf(y0.x, s_sc[cb + 0], s_sh[cb + 0])) + h0.x;
                    v[1] = eluf(fmaf(y0.y, s_sc[cb + 1], s_sh[cb + 1])) + h0.y;
                    v[2] = eluf(fmaf(y0.z, s_sc[cb + 2], s_sh[cb + 2])) + h0.z;
                    v[3] = eluf(fmaf(y0.w, s_sc[cb + 3], s_sh[cb + 3])) + h0.w;
                    v[4] = eluf(fmaf(y1.x, s_sc[cb + 4], s_sh[cb + 4])) + h1.x;
                    v[5] = eluf(fmaf(y1.y, s_sc[cb + 5], s_sh[cb + 5])) + h1.y;
                    v[6] = eluf(fmaf(y1.z, s_sc[cb + 6], s_sh[cb + 6])) + h1.z;
                    v[7] = eluf(fmaf(y1.w, s_sc[cb + 7], s_sh[cb + 7])) + h1.w;
                    *(float4*)(hp)     = make_float4(v[0], v[1], v[2], v[3]);
                    *(float4*)(hp + 4) = make_float4(v[4], v[5], v[6], v[7]);
                } else {
                    const float* ap = A + (size_t)grow * (KCH * 64) + c * 64 + gq * 8;
                    float4 f0 = *(const float4*)(ap);
                    float4 f1 = *(const float4*)(ap + 4);
                    v[0] = f0.x; v[1] = f0.y; v[2] = f0.z; v[3] = f0.w;
                    v[4] = f1.x; v[5] = f1.y; v[6] = f1.z; v[7] = f1.w;
                }
            }
            uint4 H, L;
            uint32_t* hp4 = &H.x;
            uint32_t* lp4 = &L.x;
            #pragma unroll
            for (int e = 0; e < 4; e++) {
                uint32_t b0 = __float_as_uint(v[2 * e]);
                uint32_t b1 = __float_as_uint(v[2 * e + 1]);
                hp4[e] = __byte_perm(b0, b1, 0x7632);     // {b0.hi16, b1.hi16}
                float lo0 = v[2 * e]     - __uint_as_float(b0 & 0xFFFF0000u);
                float lo1 = v[2 * e + 1] - __uint_as_float(b1 & 0xFFFF0000u);
                lp4[e] = cvt_bf16x2(lo0, lo1);
            }
            int byte = r * 128 + ((gq * 16) ^ ((r & 7) << 4));
            *(uint4*)(Ah + byte) = H;
            *(uint4*)(Al + byte) = L;
        }
        CP_ASYNC_WAIT0();
        __syncthreads();

        // ---- compute: 4 ksteps x 3 split terms x 16 mma ----
        #pragma unroll 1
        for (int ks = 0; ks < 4; ks++) {
            int k0 = ks * 32 + 4 * t;
            int k2 = k0 + 16;
            uint32_t ahi[2][4], alo[2][4];
            #pragma unroll
            for (int mt = 0; mt < 2; mt++) {
                int r0 = mrow0 + mt * 16 + g;
                int sw = (r0 & 7) << 4;
                int b0 = r0 * 128, b1 = b0 + 1024;
                ahi[mt][0] = *(const uint32_t*)(Ah + b0 + (k0 ^ sw));
                ahi[mt][1] = *(const uint32_t*)(Ah + b1 + (k0 ^ sw));
                ahi[mt][2] = *(const uint32_t*)(Ah + b0 + (k2 ^ sw));
                ahi[mt][3] = *(const uint32_t*)(Ah + b1 + (k2 ^ sw));
                alo[mt][0] = *(const uint32_t*)(Al + b0 + (k0 ^ sw));
                alo[mt][1] = *(const uint32_t*)(Al + b1 + (k0 ^ sw));
                alo[mt][2] = *(const uint32_t*)(Al + b0 + (k2 ^ sw));
                alo[mt][3] = *(const uint32_t*)(Al + b1 + (k2 ^ sw));
            }
            #pragma unroll
            for (int t3 = 0; t3 < 3; t3++) {     // hi*Bhi, lo*Bhi, hi*Blo
                const char* Bs = (t3 == 2) ? Bl : Bh;
                #pragma unroll
                for (int nt = 0; nt < 8; nt++) {
                    int n = ncol0 + nt * 8 + g;
                    int sw = (n & 7) << 4;
                    int bb = n * 128;
                    uint32_t b2[2];
                    b2[0] = *(const uint32_t*)(Bs + bb + (k0 ^ sw));
                    b2[1] = *(const uint32_t*)(Bs + bb + (k2 ^ sw));
                    mma_bf16(d[0][nt], (t3 == 1) ? alo[0] : ahi[0], b2);
                    mma_bf16(d[1][nt], (t3 == 1) ? alo[1] : ahi[1], b2);
                }
            }
        }
    }

    // ---- epilogue ----
    #pragma unroll
    for (int mt = 0; mt < 2; mt++) {
        #pragma unroll
        for (int half = 0; half < 2; half++) {
            int row = bm + mrow0 + mt * 16 + g + half * 8;
            if (MODE == 0) {
                if (row < M) {
                    #pragma unroll
                    for (int nt = 0; nt < 8; nt++) {
                        int col = ncol0 + nt * 8 + 2 * t;
                        float2 o;
                        o.x = eluf(d[mt][nt][half * 2]     + s_as[col]);
                        o.y = eluf(d[mt][nt][half * 2 + 1] + s_as[col + 1]);
                        *(float2*)(Cf + (size_t)row * HIDD + col) = o;
                    }
                }
            } else {
                float ss[4] = {0.f, 0.f, 0.f, 0.f};
                float sd[4] = {0.f, 0.f, 0.f, 0.f};
                #pragma unroll
                for (int nt = 0; nt < 8; nt++) {
                    int col = ncol0 + nt * 8 + 2 * t;
                    float dA = d[mt][nt][half * 2];
                    float dB = d[mt][nt][half * 2 + 1];
                    if (row < M)
                        *(__half2*)(Ch + (size_t)row * HIDD + col) = __floats2half2_rn(dA, dB);
                    int hh = nt >> 1;
                    ss[hh] = fmaf(dA, s_as[col], fmaf(dB, s_as[col + 1], ss[hh]));
                    sd[hh] = fmaf(dA, s_ad[col], fmaf(dB, s_ad[col + 1], sd[hh]));
                }
                #pragma unroll
                for (int e = 0; e < 4; e++) {
                    ss[e] += __shfl_xor_sync(0xffffffffu, ss[e], 1);
                    ss[e] += __shfl_xor_sync(0xffffffffu, ss[e], 2);
                    sd[e] += __shfl_xor_sync(0xffffffffu, sd[e], 1);
                    sd[e] += __shfl_xor_sync(0xffffffffu, sd[e], 2);
                }
                if (t == 0 && row < M) {
                    int h0 = ncol0 >> 4;
                    *(float4*)(alsrc + row * 8 + h0) = make_float4(ss[0], ss[1], ss[2], ss[3]);
                    *(float4*)(aldst + row * 8 + h0) = make_float4(sd[0], sd[1], sd[2], sd[3]);
                }
            }
        }
    }
}

// ---------- persistent single-pass softmax aggregate + fused BN channel sums ----------
__global__ __launch_bounds__(256)
void gat_agg_kernel(const __half* __restrict__ h2, const float* __restrict__ alsrc,
                    const float* __restrict__ aldst, const int* __restrict__ rowptr,
                    const int* __restrict__ colidx, const float* __restrict__ convb,
                    float* __restrict__ y, float* __restrict__ bnsum,
                    float* __restrict__ bnsq) {
    int tid = threadIdx.x, wid = tid >> 5, lane = tid & 31;
    int hd = lane >> 2;
    const float4 cb = *(const float4*)(convb + lane * 4);

    float4 S = make_float4(0.f, 0.f, 0.f, 0.f);
    float4 Q = make_float4(0.f, 0.f, 0.f, 0.f);

    int stride = gridDim.x * 8;
    for (int node = blockIdx.x * 8 + wid; node < NN; node += stride) {
        float adn = aldst[node * HEADS + hd];
        float wself = __expf(lrelu02(alsrc[node * HEADS + hd] + adn));
        float denom = wself;

        uint2 hvr = *(const uint2*)(h2 + (size_t)node * HIDD + lane * 4);
        float2 v0 = __half22float2(*reinterpret_cast<__half2*>(&hvr.x));
        float2 v1 = __half22float2(*reinterpret_cast<__half2*>(&hvr.y));
        float4 acc = make_float4(wself * v0.x, wself * v0.y, wself * v1.x, wself * v1.y);

        int s0 = rowptr[node], s1 = rowptr[node + 1];
        #pragma unroll 4
        for (int i = s0; i < s1; i++) {
            int s = colidx[i];
            float wgt = __expf(lrelu02(alsrc[s * HEADS + hd] + adn));
            denom += wgt;
            uint2 ur = *(const uint2*)(h2 + (size_t)s * HIDD + lane * 4);
            float2 u0 = __half22float2(*reinterpret_cast<__half2*>(&ur.x));
            float2 u1 = __half22float2(*reinterpret_cast<__half2*>(&ur.y));
            acc.x = fmaf(wgt, u0.x, acc.x);
            acc.y = fmaf(wgt, u0.y, acc.y);
            acc.z = fmaf(wgt, u1.x, acc.z);
            acc.w = fmaf(wgt, u1.y, acc.w);
        }
        float inv = 1.f / (denom + 1e-16f);
        float4 o = make_float4(acc.x * inv + cb.x, acc.y * inv + cb.y,
                               acc.z * inv + cb.z, acc.w * inv + cb.w);
        *(float4*)(y + (size_t)node * HIDD + lane * 4) = o;
        S.x += o.x; S.y += o.y; S.z += o.z; S.w += o.w;
        Q.x = fmaf(o.x, o.x, Q.x); Q.y = fmaf(o.y, o.y, Q.y);
        Q.z = fmaf(o.z, o.z, Q.z); Q.w = fmaf(o.w, o.w, Q.w);
    }

    __shared__ float4 red[2][8][32];
    red[0][wid][lane] = S;
    red[1][wid][lane] = Q;
    __syncthreads();
    if (wid < 2) {
        float4 a = red[wid][0][lane];
        #pragma unroll
        for (int w = 1; w < 8; w++) {
            float4 b = red[wid][w][lane];
            a.x += b.x; a.y += b.y; a.z += b.z; a.w += b.w;
        }
        float* dst = wid ? bnsq : bnsum;
        atomicAdd(&dst[lane * 4 + 0], a.x);
        atomicAdd(&dst[lane * 4 + 1], a.y);
        atomicAdd(&dst[lane * 4 + 2], a.z);
        atomicAdd(&dst[lane * 4 + 3], a.w);
    }
}

// ---- tail: bn apply (inline bn_final) + fused fc + re-zero fill for next launch ----
__global__ __launch_bounds__(256)
void bn_apply_fc_kernel(const float* __restrict__ y, const float* __restrict__ bnsum,
                        const float* __restrict__ bnsq, const float* __restrict__ bg,
                        const float* __restrict__ bb, float* __restrict__ h,
                        const float* __restrict__ fcw, const float* __restrict__ fcb,
                        float* __restrict__ out, int* __restrict__ fill) {
    __shared__ float s_sc[HIDD], s_sh[HIDD];
    int tid = threadIdx.x;
    int g2 = blockIdx.x * 256 + tid;
    if (g2 < NN) fill[g2] = 0;          // histogram zero for next launch
    if (tid < HIDD) {
        float mu  = bnsum[tid] * (1.f / NN);
        float var = bnsq[tid] * (1.f / NN) - mu * mu;
        float sc  = bg[tid] * rsqrtf(var + 1e-5f);
        s_sc[tid] = sc;
        s_sh[tid] = bb[tid] - mu * sc;
    }
    __syncthreads();
    int node = blockIdx.x * 8 + (tid >> 5);
    if (node >= NN) return;
    int lane = tid & 31;
    int c0 = lane * 4;
    size_t off = (size_t)node * HIDD + c0;
    float4 yv = *(const float4*)(y + off);
    float4 hv = *(const float4*)(h + off);
    float4 o;
    o.x = eluf(fmaf(yv.x, s_sc[c0 + 0], s_sh[c0 + 0])) + hv.x;
    o.y = eluf(fmaf(yv.y, s_sc[c0 + 1], s_sh[c0 + 1])) + hv.y;
    o.z = eluf(fmaf(yv.z, s_sc[c0 + 2], s_sh[c0 + 2])) + hv.z;
    o.w = eluf(fmaf(yv.w, s_sc[c0 + 3], s_sh[c0 + 3])) + hv.w;
    float4 wv = *(const float4*)(fcw + c0);
    float s = o.x * wv.x + o.y * wv.y + o.z * wv.z + o.w * wv.w;
    #pragma unroll
    for (int k = 16; k; k >>= 1) s += __shfl_xor_sync(0xffffffffu, s, k);
    if (lane == 0) out[node] = s + fcb[0];
}

// ---------------- launch ----------------
extern "C" void kernel_launch(void* const* d_in, const int* in_sizes, int n_in,
                              void* d_out, int out_size) {
    const float* x       = (const float*)d_in[0];
    const int*   ei      = (const int*)  d_in[1];
    const float* proj_w  = (const float*)d_in[2];
    const float* proj_b  = (const float*)d_in[3];
    const float* Wl      = (const float*)d_in[4];
    const float* att_src = (const float*)d_in[5];
    const float* att_dst = (const float*)d_in[6];
    const float* conv_b  = (const float*)d_in[7];
    const float* bn_g    = (const float*)d_in[8];
    const float* bn_b    = (const float*)d_in[9];
    const float* fc_w    = (const float*)d_in[10];
    const float* fc_b    = (const float*)d_in[11];
    float* out = (float*)d_out;

    int E = in_sizes[1] / 2;
    const int* srcA = ei;
    const int* dstA = ei + E;

    float *p_h, *p_y, *p_alsrc, *p_aldst, *p_bnsum, *p_bnsq;
    __half* p_h2;
    __nv_bfloat16 *p_bhi, *p_blo;
    int *p_rowptr, *p_fill, *p_col, *p_bsums;
    cudaGetSymbolAddress((void**)&p_h,      g_h);
    cudaGetSymbolAddress((void**)&p_h2,     g_h2);
    cudaGetSymbolAddress((void**)&p_y,      g_y);
    cudaGetSymbolAddress((void**)&p_alsrc,  g_alsrc);
    cudaGetSymbolAddress((void**)&p_aldst,  g_aldst);
    cudaGetSymbolAddress((void**)&p_rowptr, g_rowptr);
    cudaGetSymbolAddress((void**)&p_fill,   g_fill);
    cudaGetSymbolAddress((void**)&p_col,    g_col);
    cudaGetSymbolAddress((void**)&p_bsums,  g_bsums);
    cudaGetSymbolAddress((void**)&p_bnsum,  g_bnsum);
    cudaGetSymbolAddress((void**)&p_bnsq,   g_bnsq);
    cudaGetSymbolAddress((void**)&p_bhi,    g_Bhi);
    cudaGetSymbolAddress((void**)&p_blo,    g_Blo);

    const int SMEM_GEMM = 65536;
    cudaFuncSetAttribute(tc_gemm_kernel<4, 0>,
                         cudaFuncAttributeMaxDynamicSharedMemorySize, SMEM_GEMM);
    cudaFuncSetAttribute(tc_gemm_kernel<2, 1>,
                         cudaFuncAttributeMaxDynamicSharedMemorySize, SMEM_GEMM);
    cudaFuncSetAttribute(tc_gemm_kernel<2, 2>,
                         cudaFuncAttributeMaxDynamicSharedMemorySize, SMEM_GEMM);

    int mblk = (NN + 127) / 128;
    int eblk = (E + 255) / 256;
    const int AGG_GRID = 1184;

    // ---- fork: CSR chain on side stream, concurrent with weight-prep + GEMMs ----
    cudaStream_t s2;
    cudaStreamCreateWithFlags(&s2, cudaStreamNonBlocking);
    cudaEvent_t evFork, evJoin;
    cudaEventCreateWithFlags(&evFork, cudaEventDisableTiming);
    cudaEventCreateWithFlags(&evJoin, cudaEventDisableTiming);
    cudaEventRecord(evFork, 0);
    cudaStreamWaitEvent(s2, evFork, 0);

    // side stream: CSR build (fill is zero at entry; tail re-zeros each launch)
    hist_kernel<<<eblk, 256, 0, s2>>>(dstA, p_fill, E);
    int nblk = (NN + 1023) / 1024;
    scan_block_kernel<<<nblk, 1024, 0, s2>>>(p_fill, p_rowptr, p_bsums, NN);
    scan_add_kernel<<<nblk, 1024, 0, s2>>>(p_rowptr, p_fill, p_bsums, NN, E);
    scatter_kernel<<<eblk, 256, 0, s2>>>(srcA, dstA, p_fill, p_col, E);
    cudaEventRecord(evJoin, s2);

    // main stream: weight prep (fast) + proj + layer-0 GEMM
    prep_w_kernel<<<320, 256>>>(proj_w, Wl, p_bhi, p_blo, p_bnsum, p_bnsq);
    tc_gemm_kernel<4, 0><<<mblk, 256, SMEM_GEMM>>>(
        (float*)x, nullptr, nullptr, nullptr, nullptr, nullptr,
        p_bhi, p_blo, proj_b, nullptr, p_h, nullptr, nullptr, nullptr, NN);
    tc_gemm_kernel<2, 1><<<mblk, 256, SMEM_GEMM>>>(
        p_h, nullptr, nullptr, nullptr, nullptr, nullptr,
        p_bhi + 32768, p_blo + 32768,
        att_src, att_dst, nullptr, p_h2, p_alsrc, p_aldst, NN);

    cudaStreamWaitEvent(0, evJoin, 0);   // CSR ready before first aggregate

    for (int l = 0; l < LAYERS; l++) {
        if (l > 0) {
            // fused: h = elu(y*sc+sh)+h (BN of layer l-1) inside the A-fill
            tc_gemm_kernel<2, 2><<<mblk, 256, SMEM_GEMM>>>(
                p_h, p_y, p_bnsum + (l - 1) * HIDD, p_bnsq + (l - 1) * HIDD,
                bn_g + (l - 1) * HIDD, bn_b + (l - 1) * HIDD,
                p_bhi + 32768 + l * 16384, p_blo + 32768 + l * 16384,
                att_src + l * HEADS * CC, att_dst + l * HEADS * CC,
                nullptr, p_h2, p_alsrc, p_aldst, NN);
        }
        gat_agg_kernel<<<AGG_GRID, 256>>>(p_h2, p_alsrc, p_aldst, p_rowptr, p_col,
                                          conv_b + l * HIDD, p_y,
                                          p_bnsum + l * HIDD, p_bnsq + l * HIDD);
    }

    // ---- tail: BN(layer 2) + residual + fc + fill re-zero ----
    bn_apply_fc_kernel<<<(NN + 7) / 8, 256>>>(
        p_y, p_bnsum + 2 * HIDD, p_bnsq + 2 * HIDD, bn_g + 2 * HIDD, bn_b + 2 * HIDD,
        p_h, fc_w, fc_b, out, p_fill);

    cudaEventDestroy(evFork);
    cudaEventDestroy(evJoin);
    cudaStreamDestroy(s2);
}